// round 6
// baseline (speedup 1.0000x reference)
#include <cuda_runtime.h>
#include <math_constants.h>
#include <cstdint>

// ---------------------------------------------------------------------------
// Problem constants
// ---------------------------------------------------------------------------
#define T_MAX   8192
#define C_DIM   2048
#define N_HEAD  16
#define N_KVH   4
#define HDIM    128
#define WIN     1024
#define RMS_EPS 1.1920929e-07f

// ---------------------------------------------------------------------------
// Scratch (device globals; no runtime allocation allowed)
// ---------------------------------------------------------------------------
__device__ float g_q[(size_t)T_MAX * 2048];         // x @ Wq, [T, 2048]
__device__ float g_k[(size_t)T_MAX * 512];          // x @ Wk, [T, 512]
__device__ float g_v[(size_t)T_MAX * 512];          // x @ Wv, [T, 512]
__device__ float g_Qh[(size_t)N_HEAD * T_MAX * HDIM];   // [H][T][D]
__device__ float g_Kh[(size_t)N_KVH  * T_MAX * HDIM];   // [Hk][T][D]
__device__ float g_Vh[(size_t)N_KVH  * T_MAX * HDIM];   // [Hk][T][D]
__device__ float g_Y[(size_t)T_MAX * 2048];         // attention out [T, 2048]

// ---------------------------------------------------------------------------
// Fast SGEMM (plain fp32): C[M,N] = A[M,K] @ B[K,N], row-major.
// 128x128 block tile, BK=16, 256 threads, 8x8 per thread (split 4+4).
// Used for Q projection and the output projection (smooth-noise paths).
// ---------------------------------------------------------------------------
__global__ __launch_bounds__(256) void sgemm_kernel(
    const float* __restrict__ A, const float* __restrict__ B,
    float* __restrict__ C, int M, int N, int K)
{
    __shared__ float As[16][132];   // transposed A tile, padded
    __shared__ float Bs[16][128];

    const int tid = threadIdx.x;
    const int tx  = tid & 15;
    const int ty  = tid >> 4;
    const int bx  = blockIdx.x;
    const int by  = blockIdx.y;

    const float* Ab = A + (size_t)by * 128 * K;
    const float* Bb = B + (size_t)bx * 128;

    const int arow = tid >> 2;         // 0..63
    const int acol = (tid & 3) << 2;   // 0,4,8,12
    const int brow = tid >> 5;         // 0..7
    const int bcol = (tid & 31) << 2;  // 0..124

    float acc[8][8];
#pragma unroll
    for (int i = 0; i < 8; i++)
#pragma unroll
        for (int j = 0; j < 8; j++) acc[i][j] = 0.f;

    for (int k0 = 0; k0 < K; k0 += 16) {
        float4 a0 = *(const float4*)(Ab + (size_t)arow * K + k0 + acol);
        float4 a1 = *(const float4*)(Ab + (size_t)(arow + 64) * K + k0 + acol);
        float4 b0 = *(const float4*)(Bb + (size_t)(k0 + brow) * N + bcol);
        float4 b1 = *(const float4*)(Bb + (size_t)(k0 + brow + 8) * N + bcol);

        As[acol + 0][arow]      = a0.x;
        As[acol + 1][arow]      = a0.y;
        As[acol + 2][arow]      = a0.z;
        As[acol + 3][arow]      = a0.w;
        As[acol + 0][arow + 64] = a1.x;
        As[acol + 1][arow + 64] = a1.y;
        As[acol + 2][arow + 64] = a1.z;
        As[acol + 3][arow + 64] = a1.w;
        *(float4*)&Bs[brow][bcol]     = b0;
        *(float4*)&Bs[brow + 8][bcol] = b1;
        __syncthreads();

#pragma unroll
        for (int k = 0; k < 16; k++) {
            float4 ra0 = *(const float4*)&As[k][ty * 4];
            float4 ra1 = *(const float4*)&As[k][64 + ty * 4];
            float4 rb0 = *(const float4*)&Bs[k][tx * 4];
            float4 rb1 = *(const float4*)&Bs[k][64 + tx * 4];
            float av[8] = {ra0.x, ra0.y, ra0.z, ra0.w, ra1.x, ra1.y, ra1.z, ra1.w};
            float bv[8] = {rb0.x, rb0.y, rb0.z, rb0.w, rb1.x, rb1.y, rb1.z, rb1.w};
#pragma unroll
            for (int i = 0; i < 8; i++)
#pragma unroll
                for (int j = 0; j < 8; j++)
                    acc[i][j] += av[i] * bv[j];
        }
        __syncthreads();
    }

#pragma unroll
    for (int i = 0; i < 8; i++) {
        int r = by * 128 + ((i < 4) ? (ty * 4 + i) : (64 + ty * 4 + i - 4));
        float4 c0 = make_float4(acc[i][0], acc[i][1], acc[i][2], acc[i][3]);
        float4 c1 = make_float4(acc[i][4], acc[i][5], acc[i][6], acc[i][7]);
        *(float4*)(C + (size_t)r * N + bx * 128 + tx * 4)      = c0;
        *(float4*)(C + (size_t)r * N + bx * 128 + 64 + tx * 4) = c1;
    }
}

// ---------------------------------------------------------------------------
// K/V projection SGEMM emulating an LLVM-vectorized CPU reduction:
// 16 interleaved partial accumulators (partial[j] sums k ≡ j mod 16, ascending,
// FMA), folded at the end as the LLVM pairwise tree:
//   w[l]  = (p[l] + p[4+l]) + (p[8+l] + p[12+l])      (vector adds)
//   res   = (w[0] + w[1]) + (w[2] + w[3])             (pairwise horizontal)
// This is the accumulation structure of XLA-CPU's vectorized dot on a
// 128-bit-SIMD aarch64 host (VF=4, interleave=4).
// 32x32 block tile, BK=16, 256 threads, 4 rows x 1 col per thread.
// ---------------------------------------------------------------------------
__global__ __launch_bounds__(256) void sgemm_kv_kernel(
    const float* __restrict__ A, const float* __restrict__ B,
    float* __restrict__ C, int M, int N, int K)
{
    __shared__ float As[16][40];    // [k][m], padded (40 % 4 == 0 for float4)
    __shared__ float Bs[16][33];    // [k][n]

    const int tid = threadIdx.x;
    const int tx  = tid & 31;       // n within tile
    const int ty  = tid >> 5;       // row group (4 rows each)
    const int bx  = blockIdx.x;
    const int by  = blockIdx.y;

    const float* Ab = A + (size_t)(by * 32) * K;
    const float* Bb = B + (size_t)(bx * 32);

    // A loads: 32 m x 16 k, float2 along k per thread
    const int am = tid >> 3;            // 0..31
    const int ak = (tid & 7) << 1;      // 0,2,...,14
    // B loads: 16 k x 32 n, float2 along n per thread
    const int bk = tid >> 4;            // 0..15
    const int bn = (tid & 15) << 1;     // 0,2,...,30

    float part[4][16];
#pragma unroll
    for (int r = 0; r < 4; r++)
#pragma unroll
        for (int j = 0; j < 16; j++) part[r][j] = 0.f;

    for (int k0 = 0; k0 < K; k0 += 16) {
        float2 a = *(const float2*)(Ab + (size_t)am * K + k0 + ak);
        float2 b = *(const float2*)(Bb + (size_t)(k0 + bk) * N + bn);
        As[ak][am]     = a.x;
        As[ak + 1][am] = a.y;
        Bs[bk][bn]     = b.x;
        Bs[bk][bn + 1] = b.y;
        __syncthreads();

#pragma unroll
        for (int j = 0; j < 16; j++) {
            float4 av = *(const float4*)&As[j][ty * 4];
            float  bv = Bs[j][tx];
            part[0][j] = __fmaf_rn(av.x, bv, part[0][j]);
            part[1][j] = __fmaf_rn(av.y, bv, part[1][j]);
            part[2][j] = __fmaf_rn(av.z, bv, part[2][j]);
            part[3][j] = __fmaf_rn(av.w, bv, part[3][j]);
        }
        __syncthreads();
    }

    // LLVM-style pairwise fold of the 16 interleaved partials
#pragma unroll
    for (int r = 0; r < 4; r++) {
        float w[4];
#pragma unroll
        for (int l = 0; l < 4; l++)
            w[l] = __fadd_rn(__fadd_rn(part[r][l],     part[r][4 + l]),
                             __fadd_rn(part[r][8 + l], part[r][12 + l]));
        float res = __fadd_rn(__fadd_rn(w[0], w[1]), __fadd_rn(w[2], w[3]));
        C[(size_t)(by * 32 + ty * 4 + r) * N + bx * 32 + tx] = res;
    }
}

// Accurate rsqrt mimicking XLA's lowering: 1.0f / sqrtf(x), both RN.
__device__ __forceinline__ float rsqrt_rn(float x) {
    return __fdiv_rn(1.0f, __fsqrt_rn(x));
}

// ---------------------------------------------------------------------------
// RoPE + RMS for Q. grid (T, H), 64 threads (each owns pair d, d+64).
// ---------------------------------------------------------------------------
__global__ void rope_rms_q_kernel(
    const float* __restrict__ X, const float* __restrict__ cosb,
    const float* __restrict__ sinb, float* __restrict__ Qo, int T)
{
    const int t = blockIdx.x, h = blockIdx.y, d = threadIdx.x;
    const float* row = X + (size_t)t * 2048 + h * 128;
    float x1 = row[d], x2 = row[d + 64];
    float c = cosb[t * 64 + d], s = sinb[t * 64 + d];
    float o1 = __fadd_rn(__fmul_rn(x1, c), __fmul_rn(x2, s));
    float o2 = __fsub_rn(__fmul_rn(x2, c), __fmul_rn(x1, s));

    float ss = __fadd_rn(__fmul_rn(o1, o1), __fmul_rn(o2, o2));
#pragma unroll
    for (int o = 16; o > 0; o >>= 1) ss += __shfl_down_sync(0xffffffffu, ss, o);
    __shared__ float sh[2];
    if ((d & 31) == 0) sh[d >> 5] = ss;
    __syncthreads();
    float ms = __fmul_rn(__fadd_rn(sh[0], sh[1]), 0.0078125f);  // /128 exact
    float r = rsqrt_rn(__fadd_rn(ms, RMS_EPS));

    float* out = Qo + ((size_t)h * T + t) * 128;
    out[d]      = __fmul_rn(o1, r);
    out[d + 64] = __fmul_rn(o2, r);
}

// ---------------------------------------------------------------------------
// RoPE + RMS + 3-bit quant-dequant for K. grid (T, Hk), 64 threads.
// All RN intrinsics to mimic the reference fp32 op sequence exactly.
// ---------------------------------------------------------------------------
__global__ void rope_rms_quant_k_kernel(
    const float* __restrict__ X, const float* __restrict__ cosb,
    const float* __restrict__ sinb, float* __restrict__ Ko, int T)
{
    const int t = blockIdx.x, h = blockIdx.y, d = threadIdx.x;
    const float* row = X + (size_t)t * 512 + h * 128;
    float x1 = row[d], x2 = row[d + 64];
    float c = cosb[t * 64 + d], s = sinb[t * 64 + d];
    float o1 = __fadd_rn(__fmul_rn(x1, c), __fmul_rn(x2, s));
    float o2 = __fsub_rn(__fmul_rn(x2, c), __fmul_rn(x1, s));

    __shared__ float sh[4];
    float ss = __fadd_rn(__fmul_rn(o1, o1), __fmul_rn(o2, o2));
#pragma unroll
    for (int o = 16; o > 0; o >>= 1) ss += __shfl_down_sync(0xffffffffu, ss, o);
    if ((d & 31) == 0) sh[d >> 5] = ss;
    __syncthreads();
    float ms = __fmul_rn(__fadd_rn(sh[0], sh[1]), 0.0078125f);
    float r = rsqrt_rn(__fadd_rn(ms, RMS_EPS));
    float k1 = __fmul_rn(o1, r), k2 = __fmul_rn(o2, r);

    // quant-dequant, qmax = 3, per-token-per-head over 128 dims.
    float m = fmaxf(fabsf(k1), fabsf(k2));
#pragma unroll
    for (int o = 16; o > 0; o >>= 1) m = fmaxf(m, __shfl_down_sync(0xffffffffu, m, o));
    if ((d & 31) == 0) sh[2 + (d >> 5)] = m;
    __syncthreads();
    float sq = fmaxf(__fdiv_rn(fmaxf(sh[2], sh[3]), 3.0f), 1e-8f);
    float q1 = __fmul_rn(fminf(fmaxf(rintf(__fdiv_rn(k1, sq)), -3.f), 3.f), sq);
    float q2 = __fmul_rn(fminf(fmaxf(rintf(__fdiv_rn(k2, sq)), -3.f), 3.f), sq);

    float* out = Ko + ((size_t)h * T + t) * 128;
    out[d]      = q1;
    out[d + 64] = q2;
}

// ---------------------------------------------------------------------------
// 3-bit quant-dequant for V (no rope/rms). grid (T, Hk), 64 threads.
// ---------------------------------------------------------------------------
__global__ void quant_v_kernel(
    const float* __restrict__ X, float* __restrict__ Vo, int T)
{
    const int t = blockIdx.x, h = blockIdx.y, d = threadIdx.x;
    const float* row = X + (size_t)t * 512 + h * 128;
    float v1 = row[d], v2 = row[d + 64];

    __shared__ float sh[2];
    float m = fmaxf(fabsf(v1), fabsf(v2));
#pragma unroll
    for (int o = 16; o > 0; o >>= 1) m = fmaxf(m, __shfl_down_sync(0xffffffffu, m, o));
    if ((d & 31) == 0) sh[d >> 5] = m;
    __syncthreads();
    float sq = fmaxf(__fdiv_rn(fmaxf(sh[0], sh[1]), 3.0f), 1e-8f);
    float q1 = __fmul_rn(fminf(fmaxf(rintf(__fdiv_rn(v1, sq)), -3.f), 3.f), sq);
    float q2 = __fmul_rn(fminf(fmaxf(rintf(__fdiv_rn(v2, sq)), -3.f), 3.f), sq);

    float* out = Vo + ((size_t)h * T + t) * 128;
    out[d]      = q1;
    out[d + 64] = q2;
}

// ---------------------------------------------------------------------------
// Sliding-window flash attention (exact fp32).
// Block: one head, 64 queries. Key blocks of 64 over [max(0,t0-1024), t0+63].
// Scale applied AFTER the S matmul (as reference). Online softmax.
// ---------------------------------------------------------------------------
#define ATT_SMEM_FLOATS (8192 + 8320 + 4160 + 192)

__global__ __launch_bounds__(256) void attn_kernel(
    const float* __restrict__ Q, const float* __restrict__ K,
    const float* __restrict__ V, float* __restrict__ Y, int T)
{
    extern __shared__ float smem[];
    float* sQ  = smem;           // 64*128
    float* sKV = sQ + 8192;      // max(128*65, 64*128) = 8320
    float* sS  = sKV + 8320;     // 64*65
    float* sM  = sS + 4160;
    float* sL  = sM + 64;
    float* sC  = sL + 64;

    const int tid  = threadIdx.x;
    const int h    = blockIdx.y;
    const int t0   = blockIdx.x << 6;
    const int hk   = h >> 2;                    // GQA: q head h -> kv head h/4
    const int lane = tid & 31;
    const int wr   = tid >> 5;                  // warp id: rows wr*8..wr*8+7

    const float* Qh = Q + ((size_t)h * T + t0) * 128;
    const float* Kh = K + (size_t)hk * T * 128;
    const float* Vh = V + (size_t)hk * T * 128;

    const float scale = 0.08838834764831845f;   // 1/sqrt(128)
    for (int i = tid; i < 2048; i += 256)
        ((float4*)sQ)[i] = ((const float4*)Qh)[i];
    if (tid < 64) { sM[tid] = -CUDART_INF_F; sL[tid] = 0.f; }

    float o[8][4];
#pragma unroll
    for (int i = 0; i < 8; i++)
#pragma unroll
        for (int j = 0; j < 4; j++) o[i][j] = 0.f;

    __syncthreads();

    int kb0 = t0 - WIN; if (kb0 < 0) kb0 = 0;
    for (int kb = kb0; kb <= t0; kb += 64) {
        // ---- load K tile transposed: sKV[d][tt], stride 65 ----
        const float* Kb = Kh + (size_t)kb * 128;
        for (int i = tid; i < 8192; i += 256) {
            int tt = i >> 7, d = i & 127;
            sKV[d * 65 + tt] = Kb[i];
        }
        __syncthreads();

        // ---- S = Q @ K^T : 64x64, thread: 4 rows x 4 cols ----
        {
            const int txs = tid & 15, tys = tid >> 4;
            float acc[4][4];
#pragma unroll
            for (int i = 0; i < 4; i++)
#pragma unroll
                for (int j = 0; j < 4; j++) acc[i][j] = 0.f;
            const float* q0 = sQ + (tys * 4) * 128;
#pragma unroll 4
            for (int d = 0; d < 128; d++) {
                float kv0 = sKV[d * 65 + txs];
                float kv1 = sKV[d * 65 + txs + 16];
                float kv2 = sKV[d * 65 + txs + 32];
                float kv3 = sKV[d * 65 + txs + 48];
#pragma unroll
                for (int i = 0; i < 4; i++) {
                    float qv = q0[i * 128 + d];
                    acc[i][0] += qv * kv0;
                    acc[i][1] += qv * kv1;
                    acc[i][2] += qv * kv2;
                    acc[i][3] += qv * kv3;
                }
            }
#pragma unroll
            for (int i = 0; i < 4; i++)
#pragma unroll
                for (int j = 0; j < 4; j++)
                    sS[(tys * 4 + i) * 65 + txs + 16 * j] = acc[i][j];
        }
        __syncthreads();

        // ---- softmax (warps 0-1) overlapped with V load (warps 2-7) ----
        if (tid < 64) {
            const int r = tid, qpos = t0 + r;
            float mold = sM[r], mnew = mold;
#pragma unroll 8
            for (int j = 0; j < 64; j++) {
                int kpos = kb + j;
                bool valid = (kpos <= qpos) && (kpos + WIN > qpos);
                float x = valid ? sS[r * 65 + j] * scale : -CUDART_INF_F;
                sS[r * 65 + j] = x;
                mnew = fmaxf(mnew, x);
            }
            float c, l = sL[r];
            if (mnew == -CUDART_INF_F) {
                c = 1.f;
#pragma unroll 8
                for (int j = 0; j < 64; j++) sS[r * 65 + j] = 0.f;
            } else {
                c = (mold == -CUDART_INF_F) ? 0.f : __expf(mold - mnew);
                float sum = 0.f;
#pragma unroll 8
                for (int j = 0; j < 64; j++) {
                    float x = sS[r * 65 + j];
                    float p = (x == -CUDART_INF_F) ? 0.f : __expf(x - mnew);
                    sum += p;
                    sS[r * 65 + j] = p;
                }
                l = l * c + sum;
            }
            sM[r] = mnew; sL[r] = l; sC[r] = c;
        } else {
            const float4* Vb = (const float4*)(Vh + (size_t)kb * 128);
            for (int i = tid - 64; i < 2048; i += 192)
                ((float4*)sKV)[i] = Vb[i];
        }
        __syncthreads();

        // ---- O = O*c + P @ V ----
        {
#pragma unroll
            for (int rr = 0; rr < 8; rr++) {
                float c = sC[wr * 8 + rr];
                o[rr][0] *= c; o[rr][1] *= c; o[rr][2] *= c; o[rr][3] *= c;
            }
#pragma unroll 4
            for (int j = 0; j < 64; j++) {
                float v0 = sKV[j * 128 + lane];
                float v1 = sKV[j * 128 + lane + 32];
                float v2 = sKV[j * 128 + lane + 64];
                float v3 = sKV[j * 128 + lane + 96];
#pragma unroll
                for (int rr = 0; rr < 8; rr++) {
                    float p = sS[(wr * 8 + rr) * 65 + j];
                    o[rr][0] += p * v0;
                    o[rr][1] += p * v1;
                    o[rr][2] += p * v2;
                    o[rr][3] += p * v3;
                }
            }
        }
        __syncthreads();
    }

    // ---- epilogue: Y[t][h*128 + d] = O / l ----
#pragma unroll
    for (int rr = 0; rr < 8; rr++) {
        int r = wr * 8 + rr;
        float inv = __fdiv_rn(1.f, sL[r]);
        size_t base = (size_t)(t0 + r) * 2048 + h * 128 + lane;
        Y[base]      = o[rr][0] * inv;
        Y[base + 32] = o[rr][1] * inv;
        Y[base + 64] = o[rr][2] * inv;
        Y[base + 96] = o[rr][3] * inv;
    }
}

// ---------------------------------------------------------------------------
// Launch
// ---------------------------------------------------------------------------
extern "C" void kernel_launch(void* const* d_in, const int* in_sizes, int n_in,
                              void* d_out, int out_size)
{
    const float* x     = (const float*)d_in[0];
    const float* cosb  = (const float*)d_in[1];
    const float* sinb  = (const float*)d_in[2];
    const float* Wq    = (const float*)d_in[3];
    const float* Wk    = (const float*)d_in[4];
    const float* Wv    = (const float*)d_in[5];
    const float* Wproj = (const float*)d_in[6];
    float* out = (float*)d_out;

    const int T = in_sizes[0] / C_DIM;

    float *pq, *pk, *pv, *pQ, *pK, *pV, *pY;
    cudaGetSymbolAddress((void**)&pq, g_q);
    cudaGetSymbolAddress((void**)&pk, g_k);
    cudaGetSymbolAddress((void**)&pv, g_v);
    cudaGetSymbolAddress((void**)&pQ, g_Qh);
    cudaGetSymbolAddress((void**)&pK, g_Kh);
    cudaGetSymbolAddress((void**)&pV, g_Vh);
    cudaGetSymbolAddress((void**)&pY, g_Y);

    cudaFuncSetAttribute(attn_kernel, cudaFuncAttributeMaxDynamicSharedMemorySize,
                         ATT_SMEM_FLOATS * (int)sizeof(float));

    dim3 blk(256);
    // Q projection (fast path) + K/V projections (interleaved-16 emulation)
    sgemm_kernel<<<dim3(2048 / 128, T / 128), blk>>>(x, Wq, pq, T, 2048, 2048);
    sgemm_kv_kernel<<<dim3(512 / 32, T / 32), blk>>>(x, Wk, pk, T, 512, 2048);
    sgemm_kv_kernel<<<dim3(512 / 32, T / 32), blk>>>(x, Wv, pv, T, 512, 2048);
    // RoPE / RMS / quant
    rope_rms_q_kernel<<<dim3(T, N_HEAD), 64>>>(pq, cosb, sinb, pQ, T);
    rope_rms_quant_k_kernel<<<dim3(T, N_KVH), 64>>>(pk, cosb, sinb, pK, T);
    quant_v_kernel<<<dim3(T, N_KVH), 64>>>(pv, pV, T);
    // Attention
    attn_kernel<<<dim3(T / 64, N_HEAD), 256, ATT_SMEM_FLOATS * (int)sizeof(float)>>>(
        pQ, pK, pV, pY, T);
    // Output projection
    sgemm_kernel<<<dim3(2048 / 128, T / 128), blk>>>(pY, Wproj, out, T, 2048, 2048);
}